// round 6
// baseline (speedup 1.0000x reference)
#include <cuda_runtime.h>
#include <math.h>

#define B     4096
#define NSUB  20
#define NNEG  5
#define DIM   128
#define NIDX  (NSUB + NSUB + NSUB * NNEG)   // 140

__device__ float    g_partial[B];
__device__ unsigned g_done = 0;

__device__ __forceinline__ float log_sigmoid_f(float x) {
    return fminf(x, 0.0f) - log1pf(expf(-fabsf(x)));
}

__global__ __launch_bounds__(DIM)
void fasttext_fused_kernel(const int* __restrict__ u_pos,
                           const int* __restrict__ v_pos,
                           const int* __restrict__ v_neg,
                           const float* __restrict__ uw,
                           const float* __restrict__ vw,
                           float* __restrict__ out) {
    const int b = blockIdx.x;
    const int t = threadIdx.x;          // 0..127 = dim
    const int lane = t & 31;
    const int warp = t >> 5;

    __shared__ int s_idx[NIDX];
    if (t < NSUB)                  s_idx[t]                 = u_pos[b * NSUB + t];
    if (t >= 32 && t < 32 + NSUB)  s_idx[NSUB + (t - 32)]   = v_pos[b * NSUB + (t - 32)];
    if (t < NSUB * NNEG)           s_idx[2 * NSUB + t]      = v_neg[b * NSUB * NNEG + t];
    __syncthreads();

    // Raw sums; fold 1/NSUB^2 into the score scale at the end.
    float u_acc = 0.0f;
    float v_acc = 0.0f;
    #pragma unroll
    for (int s = 0; s < NSUB; ++s) {
        const int iu = s_idx[s];
        const int iv = s_idx[NSUB + s];
        if (iu != 0) u_acc += __ldg(uw + (long)iu * DIM + t);   // padding_idx=0
        v_acc += __ldg(vw + (long)iv * DIM + t);
    }

    float n_acc[NNEG];
    #pragma unroll
    for (int n = 0; n < NNEG; ++n) n_acc[n] = 0.0f;

    #pragma unroll
    for (int s = 0; s < NSUB; ++s) {
        #pragma unroll
        for (int n = 0; n < NNEG; ++n) {
            const int idx = s_idx[2 * NSUB + s * NNEG + n];
            n_acc[n] += __ldg(vw + (long)idx * DIM + t);
        }
    }

    // Six dot products over 128 dims.
    float p[1 + NNEG];
    p[0] = u_acc * v_acc;
    #pragma unroll
    for (int n = 0; n < NNEG; ++n) p[1 + n] = u_acc * n_acc[n];

    #pragma unroll
    for (int i = 0; i < 1 + NNEG; ++i) {
        #pragma unroll
        for (int off = 16; off > 0; off >>= 1)
            p[i] += __shfl_xor_sync(0xFFFFFFFFu, p[i], off);
    }

    __shared__ float red[1 + NNEG][4];
    if (lane == 0) {
        #pragma unroll
        for (int i = 0; i < 1 + NNEG; ++i) red[i][warp] = p[i];
    }
    __syncthreads();

    __shared__ bool s_last;
    if (t == 0) {
        const float inv_ns2 = 1.0f / (float)(NSUB * NSUB);
        float score = (red[0][0] + red[0][1] + red[0][2] + red[0][3]) * inv_ns2;
        float loss = log_sigmoid_f(score);
        #pragma unroll
        for (int n = 0; n < NNEG; ++n) {
            float ns = (red[1 + n][0] + red[1 + n][1] + red[1 + n][2] + red[1 + n][3]) * inv_ns2;
            loss += log_sigmoid_f(-ns);
        }
        g_partial[b] = loss;
        __threadfence();
        unsigned prev = atomicAdd(&g_done, 1u);
        s_last = (prev == B - 1);
    }
    __syncthreads();

    // ---- last block: deterministic fixed-order final reduction ----
    if (s_last) {
        __threadfence();
        // 4096 partials, 128 threads -> 32 each; 4 interleaved accumulators
        // (fixed combination order every run -> bit-deterministic).
        float a0 = 0.f, a1 = 0.f, a2 = 0.f, a3 = 0.f;
        #pragma unroll
        for (int k = 0; k < B / DIM; k += 4) {
            a0 += *((volatile float*)&g_partial[t + (k + 0) * DIM]);
            a1 += *((volatile float*)&g_partial[t + (k + 1) * DIM]);
            a2 += *((volatile float*)&g_partial[t + (k + 2) * DIM]);
            a3 += *((volatile float*)&g_partial[t + (k + 3) * DIM]);
        }
        __shared__ float fr[DIM];
        fr[t] = (a0 + a1) + (a2 + a3);
        __syncthreads();
        #pragma unroll
        for (int off = DIM / 2; off > 0; off >>= 1) {
            if (t < off) fr[t] += fr[t + off];
            __syncthreads();
        }
        if (t == 0) {
            out[0] = -fr[0] / (float)B;
            g_done = 0;                 // reset for next graph replay
        }
    }
}

extern "C" void kernel_launch(void* const* d_in, const int* in_sizes, int n_in,
                              void* d_out, int out_size) {
    // metadata order: u_pos, v_pos, v_neg, batch_size, u_weight, v_weight
    const int*   u_pos = (const int*)d_in[0];
    const int*   v_pos = (const int*)d_in[1];
    const int*   v_neg = (const int*)d_in[2];
    const float* uw    = (const float*)d_in[4];
    const float* vw    = (const float*)d_in[5];
    float* out = (float*)d_out;

    fasttext_fused_kernel<<<B, DIM>>>(u_pos, v_pos, v_neg, uw, vw, out);
}

// round 7
// speedup vs baseline: 1.1360x; 1.1360x over previous
#include <cuda_runtime.h>
#include <math.h>

#define B      4096
#define NSUB   20
#define NNEG   5
#define DIM    128
#define NWARPS 4                       // warps (batch elements) per block
#define GRID   (B / NWARPS)            // 1024 blocks

__device__ float    g_partial[GRID];
__device__ unsigned g_done = 0;

__device__ __forceinline__ float log_sigmoid_f(float x) {
    return fminf(x, 0.0f) - log1pf(expf(-fabsf(x)));
}

// LDG.128 with .cg (skip L1 allocate, keep L2): rows are use-once per SM.
__device__ __forceinline__ float4 ldcg_f4(const float4* p) {
    return __ldcg(p);
}

__global__ __launch_bounds__(NWARPS * 32)
void fasttext_fused_kernel(const int* __restrict__ u_pos,
                           const int* __restrict__ v_pos,
                           const int* __restrict__ v_neg,
                           const float* __restrict__ uw,
                           const float* __restrict__ vw,
                           float* __restrict__ out) {
    const int lane = threadIdx.x & 31;
    const int warp = threadIdx.x >> 5;
    const int b    = blockIdx.x * NWARPS + warp;   // batch element for this warp

    // ---- stage indices into registers (lane-strided), broadcast via shfl ----
    int iu = 0, iv = 0;
    if (lane < NSUB) {
        iu = u_pos[b * NSUB + lane];
        iv = v_pos[b * NSUB + lane];
    }
    int in0, in1, in2, in3 = 0;
    {
        const int base = b * NSUB * NNEG;
        in0 = v_neg[base + lane];
        in1 = v_neg[base + 32 + lane];
        in2 = v_neg[base + 64 + lane];
        if (lane < 4) in3 = v_neg[base + 96 + lane];
    }

    // 32-bit byte-offset addressing: tables are 512 MB (< 4 GB), row = 512 B.
    const char* uwB = (const char*)uw;
    const char* vwB = (const char*)vw;
    const unsigned laneOff = (unsigned)lane * 16u;

    float4 ua = make_float4(0.f, 0.f, 0.f, 0.f);
    float4 va = make_float4(0.f, 0.f, 0.f, 0.f);

    #pragma unroll
    for (int s = 0; s < NSUB; ++s) {
        const unsigned idx_u = (unsigned)__shfl_sync(0xFFFFFFFFu, iu, s);
        const unsigned idx_v = (unsigned)__shfl_sync(0xFFFFFFFFu, iv, s);
        if (idx_u != 0u) {                   // padding_idx = 0
            float4 r = ldcg_f4((const float4*)(uwB + (idx_u << 9) + laneOff));
            ua.x += r.x; ua.y += r.y; ua.z += r.z; ua.w += r.w;
        }
        float4 r = ldcg_f4((const float4*)(vwB + (idx_v << 9) + laneOff));
        va.x += r.x; va.y += r.y; va.z += r.z; va.w += r.w;
    }

    float4 na[NNEG];
    #pragma unroll
    for (int n = 0; n < NNEG; ++n) na[n] = make_float4(0.f, 0.f, 0.f, 0.f);

    // layout [NSUB, NNEG]: j = s*NNEG + n  ->  accumulator n = j % NNEG
    #pragma unroll
    for (int j = 0; j < NSUB * NNEG; ++j) {
        int srcI;
        if      (j < 32) srcI = __shfl_sync(0xFFFFFFFFu, in0, j);
        else if (j < 64) srcI = __shfl_sync(0xFFFFFFFFu, in1, j - 32);
        else if (j < 96) srcI = __shfl_sync(0xFFFFFFFFu, in2, j - 64);
        else             srcI = __shfl_sync(0xFFFFFFFFu, in3, j - 96);
        const unsigned src = (unsigned)srcI;
        float4 r = ldcg_f4((const float4*)(vwB + (src << 9) + laneOff));
        const int n = j % NNEG;
        na[n].x += r.x; na[n].y += r.y; na[n].z += r.z; na[n].w += r.w;
    }

    // ---- six dot products, warp-reduced ----
    float p[1 + NNEG];
    p[0] = ua.x * va.x + ua.y * va.y + ua.z * va.z + ua.w * va.w;
    #pragma unroll
    for (int n = 0; n < NNEG; ++n)
        p[1 + n] = ua.x * na[n].x + ua.y * na[n].y + ua.z * na[n].z + ua.w * na[n].w;

    #pragma unroll
    for (int i = 0; i < 1 + NNEG; ++i) {
        #pragma unroll
        for (int off = 16; off > 0; off >>= 1)
            p[i] += __shfl_xor_sync(0xFFFFFFFFu, p[i], off);
    }

    __shared__ float s_loss[NWARPS];
    if (lane == 0) {
        const float inv_ns2 = 1.0f / (float)(NSUB * NSUB);
        float loss = log_sigmoid_f(p[0] * inv_ns2);
        #pragma unroll
        for (int n = 0; n < NNEG; ++n)
            loss += log_sigmoid_f(-(p[1 + n] * inv_ns2));
        s_loss[warp] = loss;
    }
    __syncthreads();

    // ---- per-block partial, then last-block deterministic final reduce ----
    __shared__ bool s_last;
    if (threadIdx.x == 0) {
        g_partial[blockIdx.x] = s_loss[0] + s_loss[1] + s_loss[2] + s_loss[3];
        __threadfence();
        unsigned prev = atomicAdd(&g_done, 1u);
        s_last = (prev == GRID - 1);
    }
    __syncthreads();

    if (s_last) {
        __threadfence();
        const int t = threadIdx.x;               // 128 threads
        float a = 0.0f;
        #pragma unroll
        for (int k = 0; k < GRID / 128; ++k)     // fixed order: deterministic
            a += *((volatile float*)&g_partial[t + k * 128]);
        __shared__ float red[128];
        red[t] = a;
        __syncthreads();
        #pragma unroll
        for (int off = 64; off > 0; off >>= 1) {
            if (t < off) red[t] += red[t + off];
            __syncthreads();
        }
        if (t == 0) {
            out[0] = -red[0] / (float)B;
            g_done = 0;                          // reset for next graph replay
        }
    }
}

extern "C" void kernel_launch(void* const* d_in, const int* in_sizes, int n_in,
                              void* d_out, int out_size) {
    // metadata order: u_pos, v_pos, v_neg, batch_size, u_weight, v_weight
    const int*   u_pos = (const int*)d_in[0];
    const int*   v_pos = (const int*)d_in[1];
    const int*   v_neg = (const int*)d_in[2];
    const float* uw    = (const float*)d_in[4];
    const float* vw    = (const float*)d_in[5];
    float* out = (float*)d_out;

    fasttext_fused_kernel<<<GRID, NWARPS * 32>>>(u_pos, v_pos, v_neg, uw, vw, out);
}